// round 14
// baseline (speedup 1.0000x reference)
#include <cuda_runtime.h>
#include <cuda_fp16.h>
#include <cstdint>

#define NROWS 4096
#define INDIM 1024
#define DDIM  2048
#define TWOD  4096
#define NGATE 8
#define OUTDIM 1024
#define W1R   (2*(1+NGATE)*DDIM)   // 36864

// ---------------------------------------------------------------------------
// Device scratch (allocation-free rule: __device__ globals). Everything fp16.
// ---------------------------------------------------------------------------
__device__ __half g_xf [(size_t)NROWS * INDIM];
__device__ __half g_W1f[(size_t)W1R   * INDIM];
__device__ __half g_W2f[(size_t)DDIM  * TWOD];
__device__ __half g_W3f[(size_t)OUTDIM* DDIM];
__device__ __half g_sf [(size_t)NROWS * TWOD];
__device__ __half g_h2f[(size_t)NROWS * DDIM];
__device__ int g_perm[NROWS];
__device__ int g_off[NGATE + 1];

// ---------------------------------------------------------------------------
__global__ void sort_gates(const int* __restrict__ gate_ids) {
    __shared__ int cnt[NGATE];
    __shared__ int base[NGATE];
    int t = threadIdx.x;
    if (t < NGATE) cnt[t] = 0;
    __syncthreads();
    for (int i = t; i < NROWS; i += blockDim.x)
        atomicAdd(&cnt[gate_ids[i]], 1);
    __syncthreads();
    if (t == 0) {
        int a = 0;
        for (int g = 0; g < NGATE; g++) { base[g] = a; g_off[g] = a; a += cnt[g]; }
        g_off[NGATE] = a;
    }
    __syncthreads();
    for (int i = t; i < NROWS; i += blockDim.x) {
        int g = gate_ids[i];
        int p = atomicAdd(&base[g], 1);
        g_perm[p] = i;
    }
}

// ---------------------------------------------------------------------------
// fp32 -> fp16 streaming convert: 8 floats/thread/iter, 16B packed stores
// ---------------------------------------------------------------------------
__global__ __launch_bounds__(256) void conv_f32h(
    const float* __restrict__ in, __half* __restrict__ outp, int n8)
{
    const int stride = gridDim.x * 256;
    for (int i = blockIdx.x * 256 + threadIdx.x; i < n8; i += stride) {
        float4 a = reinterpret_cast<const float4*>(in)[2 * i];
        float4 b = reinterpret_cast<const float4*>(in)[2 * i + 1];
        __half2 h0 = __floats2half2_rn(a.x, a.y);
        __half2 h1 = __floats2half2_rn(a.z, a.w);
        __half2 h2 = __floats2half2_rn(b.x, b.y);
        __half2 h3 = __floats2half2_rn(b.z, b.w);
        uint4 o = make_uint4(*reinterpret_cast<uint32_t*>(&h0),
                             *reinterpret_cast<uint32_t*>(&h1),
                             *reinterpret_cast<uint32_t*>(&h2),
                             *reinterpret_cast<uint32_t*>(&h3));
        reinterpret_cast<uint4*>(outp)[i] = o;
    }
}

// ---------------------------------------------------------------------------
// Helpers (portable to base sm_103: mma.sync + cp.async + ldmatrix)
// ---------------------------------------------------------------------------
__device__ __forceinline__ uint32_t smem_u32(const void* p) {
    uint32_t a;
    asm("{ .reg .u64 t; cvta.to.shared.u64 t, %1; cvt.u32.u64 %0, t; }"
        : "=r"(a) : "l"(p));
    return a;
}
__device__ __forceinline__ void cp16(uint32_t dst, const void* src, bool pred) {
    int sz = pred ? 16 : 0;
    asm volatile("cp.async.cg.shared.global [%0], [%1], 16, %2;"
                 :: "r"(dst), "l"(src), "r"(sz) : "memory");
}
__device__ __forceinline__ void mma16816(float* c, const uint32_t* a,
                                         const uint32_t* b) {
    asm volatile(
        "mma.sync.aligned.m16n8k16.row.col.f32.f16.f16.f32 "
        "{%0,%1,%2,%3}, {%4,%5,%6,%7}, {%8,%9}, {%0,%1,%2,%3};"
        : "+f"(c[0]), "+f"(c[1]), "+f"(c[2]), "+f"(c[3])
        : "r"(a[0]), "r"(a[1]), "r"(a[2]), "r"(a[3]), "r"(b[0]), "r"(b[1]));
}
__device__ __forceinline__ void ldsm4(uint32_t* r, uint32_t addr) {
    asm volatile("ldmatrix.sync.aligned.m8n8.x4.shared.b16 {%0,%1,%2,%3}, [%4];"
                 : "=r"(r[0]), "=r"(r[1]), "=r"(r[2]), "=r"(r[3]) : "r"(addr));
}

constexpr int BM = 128, BN = 128, BK = 64;
constexpr int ROWB  = BK * 2;            // 128 bytes per smem row
constexpr int ARR   = BM * ROWB;         // 16KB per array (Af / Bf)
constexpr int STAGE = 2 * ARR;           // 32KB
constexpr int NST   = 3;
constexpr int SMEM_TOTAL = NST * STAGE;  // 96KB -> 2 CTAs/SM
constexpr int THREADS = 128;             // 4 warps, 2x2, 64x64 warp tiles

// Full 8-slot swizzle: 16B slot XOR'd by (row&7). 128B rows span all 32 banks
// -> ldmatrix 8-row groups hit 8 distinct slots: conflict-free.
// XOR applied to the FINAL column (incl. K-half offset): no carry into row.
__device__ __forceinline__ uint32_t swz_off(uint32_t row, uint32_t col) {
    return row * ROWB + (col ^ ((row & 7u) << 4));
}

// ---------------------------------------------------------------------------
// fp16 GEMM on mma.sync + ldmatrix: Out[m,n] = epi( Af[m,:].Wf[n,:] + bias )
// Epilogue: +bias, relu, *scale, += addH, fp32 store OR fp16 store.
// GATE: rows gathered/scattered via g_perm segment blockIdx.z, W offset by gate.
// ---------------------------------------------------------------------------
template<bool GATE>
__global__ __launch_bounds__(THREADS, 2)
void mma_gemm(const __half* __restrict__ Af,
              const __half* __restrict__ Wf_,
              const float* __restrict__ bias_,
              float* __restrict__ outF,
              __half* __restrict__ outH,
              const __half* __restrict__ addH,
              int Nout, int K, int do_relu, float scale)
{
    extern __shared__ char smem[];
    const uint32_t sb = smem_u32(smem);
    const int tid = threadIdx.x, wid = tid >> 5, lid = tid & 31;

    int rowStart, rowValid;
    const __half* Wf = Wf_;
    const float* bp = bias_;
    if (GATE) {
        int g = blockIdx.z;
        int s0 = g_off[g], s1 = g_off[g + 1];
        rowStart = s0 + blockIdx.y * BM;
        if (rowStart >= s1) return;
        rowValid = min(BM, s1 - rowStart);
        Wf += (size_t)g * Nout * K;
        if (bp) bp += (size_t)g * Nout;
    } else {
        rowStart = blockIdx.y * BM;
        rowValid = BM;
    }
    const int cb = blockIdx.x * BN;

    // ---- cp.async mapping: slot = tid&7 (16B), row base = tid>>3, 8 iters
    const int slot = tid & 7;
    const int r0   = tid >> 3;          // 0..15
    int  arow[8];
    bool vA[8];
    uint32_t dOf[8];
#pragma unroll
    for (int i = 0; i < 8; i++) {
        int r = r0 + 16 * i;
        int ar;
        if (GATE) { ar = (r < rowValid) ? g_perm[rowStart + r] : -1; }
        else      { ar = rowStart + r; }
        vA[i]   = ar >= 0;
        arow[i] = vA[i] ? ar : 0;
        dOf[i]  = swz_off((uint32_t)r, (uint32_t)slot * 16);
    }
    const __half* pA0 = Af + slot * 8;
    const __half* pB0 = Wf + (size_t)(cb + r0) * K + slot * 8;

    const int T = K / BK;
    auto load_tile = [&](int kt) {
        uint32_t st = sb + (kt % NST) * STAGE;
        int ke = kt * BK;
#pragma unroll
        for (int i = 0; i < 8; i++) {
            cp16(st + 0 * ARR + dOf[i], pA0 + (size_t)arow[i] * K + ke, vA[i]);
            cp16(st + 1 * ARR + dOf[i], pB0 + (size_t)(16 * i) * K + ke, true);
        }
        asm volatile("cp.async.commit_group;" ::: "memory");
    };

    float acc[4][8][4];
#pragma unroll
    for (int a = 0; a < 4; a++)
#pragma unroll
        for (int b = 0; b < 8; b++)
#pragma unroll
            for (int c = 0; c < 4; c++) acc[a][b][c] = 0.f;

    // warp tiling: 2x2 warps, 64x64 per warp
    const int wm = (wid >> 1) * 64;
    const int wn = (wid & 1) * 64;
    const int lg = lid >> 3, l7 = lid & 7;

    // ldmatrix lane components: row offset + mask separate from column so the
    // K-half offset is added BEFORE the swizzle XOR (no carry into row bits).
    uint32_t rowA[4], mskA[4], rowB[4], mskB[4];
    const uint32_t colA = (uint32_t)(lg >> 1) << 4;
    const uint32_t colB = (uint32_t)(lg & 1) << 4;
#pragma unroll
    for (int mt = 0; mt < 4; mt++) {
        uint32_t row = wm + mt * 16 + ((lg & 1) << 3) + l7;
        rowA[mt] = row * ROWB;
        mskA[mt] = (row & 7u) << 4;
    }
#pragma unroll
    for (int np = 0; np < 4; np++) {
        uint32_t row = wn + np * 16 + ((lg >> 1) << 3) + l7;
        rowB[np] = row * ROWB;
        mskB[np] = (row & 7u) << 4;
    }

    load_tile(0);
    load_tile(1);

    for (int kt = 0; kt < T; kt++) {
        if (kt < T - 1) asm volatile("cp.async.wait_group 1;" ::: "memory");
        else            asm volatile("cp.async.wait_group 0;" ::: "memory");
        __syncthreads();
        if (kt + 2 < T) load_tile(kt + 2);

        const uint32_t S = sb + (kt % NST) * STAGE;
#pragma unroll
        for (int kh = 0; kh < 4; kh++) {
            const uint32_t kof = kh * 32;
            uint32_t af[4][4], bf[4][4];
#pragma unroll
            for (int mt = 0; mt < 4; mt++) {
                uint32_t off = rowA[mt] + ((colA + kof) ^ mskA[mt]);
                ldsm4(af[mt], S + 0 * ARR + off);
            }
#pragma unroll
            for (int np = 0; np < 4; np++) {
                uint32_t off = rowB[np] + ((colB + kof) ^ mskB[np]);
                ldsm4(bf[np], S + 1 * ARR + off);
            }
#pragma unroll
            for (int mt = 0; mt < 4; mt++) {
#pragma unroll
                for (int np = 0; np < 4; np++) {
                    // np covers nt = 2np (regs 0,1) and nt = 2np+1 (regs 2,3)
                    mma16816(acc[mt][2 * np],     af[mt], &bf[np][0]);
                    mma16816(acc[mt][2 * np + 1], af[mt], &bf[np][2]);
                }
            }
        }
    }

    // ------------------------------- epilogue ------------------------------
    const int gr = lid >> 2;
#pragma unroll
    for (int mt = 0; mt < 4; mt++) {
#pragma unroll
        for (int half = 0; half < 2; half++) {
            const int rloc = wm + mt * 16 + gr + half * 8;
            int grow;
            bool valid = true;
            if (GATE) {
                valid = (rloc < rowValid);
                grow = valid ? g_perm[rowStart + rloc] : 0;
            } else {
                grow = rowStart + rloc;
            }
            if (!valid) continue;
#pragma unroll
            for (int nt = 0; nt < 8; nt++) {
                const int col = cb + wn + nt * 8 + (lid & 3) * 2;
                float v0 = acc[mt][nt][half * 2 + 0];
                float v1 = acc[mt][nt][half * 2 + 1];
                if (bp) {
                    float2 bb = *(const float2*)(bp + col);
                    v0 += bb.x; v1 += bb.y;
                }
                if (do_relu) { v0 = fmaxf(v0, 0.f); v1 = fmaxf(v1, 0.f); }
                v0 *= scale; v1 *= scale;
                const size_t rb = (size_t)grow * Nout + col;
                if (addH) {
                    uint32_t uh = *(const uint32_t*)(addH + rb);
                    float2 fh = __half22float2(*reinterpret_cast<__half2*>(&uh));
                    v0 += fh.x; v1 += fh.y;
                }
                if (outF) {
                    *(float2*)(outF + rb) = make_float2(v0, v1);
                } else {
                    uint32_t ph = (uint32_t)__half_as_ushort(__float2half_rn(v0)) |
                                  ((uint32_t)__half_as_ushort(__float2half_rn(v1)) << 16);
                    *(uint32_t*)(outH + rb) = ph;
                }
            }
        }
    }
}

// ---------------------------------------------------------------------------
extern "C" void kernel_launch(void* const* d_in, const int* in_sizes, int n_in,
                              void* d_out, int out_size) {
    const float* x   = (const float*)d_in[0];
    const int*   gid = (const int*)  d_in[1];
    const float* W1  = (const float*)d_in[2];
    const float* b1  = (const float*)d_in[3];
    const float* W2  = (const float*)d_in[4];
    const float* b2  = (const float*)d_in[5];
    const float* W3  = (const float*)d_in[6];
    float* out = (float*)d_out;

    __half *xf, *w1f, *w2f, *w3f, *sf, *h2f;
    cudaGetSymbolAddress((void**)&xf,  g_xf);
    cudaGetSymbolAddress((void**)&w1f, g_W1f);
    cudaGetSymbolAddress((void**)&w2f, g_W2f);
    cudaGetSymbolAddress((void**)&w3f, g_W3f);
    cudaGetSymbolAddress((void**)&sf,  g_sf);
    cudaGetSymbolAddress((void**)&h2f, g_h2f);

    cudaFuncSetAttribute((const void*)mma_gemm<true>,
                         cudaFuncAttributeMaxDynamicSharedMemorySize, SMEM_TOTAL);
    cudaFuncSetAttribute((const void*)mma_gemm<false>,
                         cudaFuncAttributeMaxDynamicSharedMemorySize, SMEM_TOTAL);

    sort_gates<<<1, 256>>>(gid);

    // streaming conversions: grid-stride, 8 floats/thread/iter
    auto cgrid = [](size_t elems) {
        int blocks = (int)((elems / 8 + 255) / 256);
        return blocks < 2368 ? blocks : 2368;
    };
    conv_f32h<<<cgrid((size_t)NROWS * INDIM), 256>>>(x, xf, NROWS * INDIM / 8);
    conv_f32h<<<cgrid((size_t)W1R * INDIM),   256>>>(W1, w1f, (int)((size_t)W1R * INDIM / 8));
    conv_f32h<<<cgrid((size_t)DDIM * TWOD),   256>>>(W2, w2f, DDIM * TWOD / 8);
    conv_f32h<<<cgrid((size_t)OUTDIM * DDIM), 256>>>(W3, w3f, OUTDIM * DDIM / 8);

    // L1 gate blocks: s = 0.9*relu(x @ W1_g^T + b1_g), rows scattered via perm
    mma_gemm<true><<<dim3(TWOD / BN, NROWS / BM, NGATE), THREADS, SMEM_TOTAL>>>(
        xf, w1f, b1,
        nullptr, sf, nullptr,
        TWOD, INDIM, /*relu=*/1, /*scale=*/0.9f);

    // L1 shared block: s += relu(x @ W1_sh^T + b1_sh)
    mma_gemm<false><<<dim3(TWOD / BN, NROWS / BM), THREADS, SMEM_TOTAL>>>(
        xf,
        w1f + (size_t)NGATE * TWOD * INDIM,
        b1 + (size_t)NGATE * TWOD,
        nullptr, sf, sf,
        TWOD, INDIM, /*relu=*/1, /*scale=*/1.0f);

    // L2: h2 = relu(s @ W2^T + b2)
    mma_gemm<false><<<dim3(DDIM / BN, NROWS / BM), THREADS, SMEM_TOTAL>>>(
        sf, w2f, b2,
        nullptr, h2f, nullptr,
        DDIM, TWOD, /*relu=*/1, /*scale=*/1.0f);

    // L3: out = h2 @ W3^T  (fp32 store)
    mma_gemm<false><<<dim3(OUTDIM / BN, NROWS / BM), THREADS, SMEM_TOTAL>>>(
        h2f, w3f, nullptr,
        out, nullptr, nullptr,
        OUTDIM, DDIM, /*relu=*/0, /*scale=*/1.0f);
}

// round 15
// speedup vs baseline: 1.0441x; 1.0441x over previous
#include <cuda_runtime.h>
#include <cuda_fp16.h>
#include <cstdint>

#define NROWS 4096
#define INDIM 1024
#define DDIM  2048
#define TWOD  4096
#define NGATE 8
#define OUTDIM 1024
#define W1R   (2*(1+NGATE)*DDIM)   // 36864

// ---------------------------------------------------------------------------
// Device scratch (allocation-free rule: __device__ globals). Everything fp16.
// ---------------------------------------------------------------------------
__device__ __half g_xf [(size_t)NROWS * INDIM];
__device__ __half g_W1f[(size_t)W1R   * INDIM];
__device__ __half g_W2f[(size_t)DDIM  * TWOD];
__device__ __half g_W3f[(size_t)OUTDIM* DDIM];
__device__ __half g_sf [(size_t)NROWS * TWOD];
__device__ __half g_h2f[(size_t)NROWS * DDIM];
__device__ int g_perm[NROWS];
__device__ int g_off[NGATE + 1];

// ---------------------------------------------------------------------------
__global__ void sort_gates(const int* __restrict__ gate_ids) {
    __shared__ int cnt[NGATE];
    __shared__ int base[NGATE];
    int t = threadIdx.x;
    if (t < NGATE) cnt[t] = 0;
    __syncthreads();
    for (int i = t; i < NROWS; i += blockDim.x)
        atomicAdd(&cnt[gate_ids[i]], 1);
    __syncthreads();
    if (t == 0) {
        int a = 0;
        for (int g = 0; g < NGATE; g++) { base[g] = a; g_off[g] = a; a += cnt[g]; }
        g_off[NGATE] = a;
    }
    __syncthreads();
    for (int i = t; i < NROWS; i += blockDim.x) {
        int g = gate_ids[i];
        int p = atomicAdd(&base[g], 1);
        g_perm[p] = i;
    }
}

// ---------------------------------------------------------------------------
// Fused fp32 -> fp16 conversion for all 4 tensors, one chunk (8 floats) per
// thread, streaming loads/stores (__ldcs/__stcs: no L2 pollution, max MLP).
// Region boundaries in 8-elem chunks (compile-time).
// ---------------------------------------------------------------------------
constexpr int C_X  = NROWS * INDIM / 8;                    // 524288
constexpr int C_W1 = C_X  + (int)((size_t)W1R * INDIM / 8);  // +4718592
constexpr int C_W2 = C_W1 + DDIM * TWOD / 8;               // +1048576
constexpr int C_W3 = C_W2 + OUTDIM * DDIM / 8;             // +262144
constexpr int CONV_BLOCKS = C_W3 / 32;                     // 256 thr = 32 chunks... no: 1 chunk/thread

__global__ __launch_bounds__(256) void conv_all(
    const float* __restrict__ x,  const float* __restrict__ W1,
    const float* __restrict__ W2, const float* __restrict__ W3,
    __half* __restrict__ xf,  __half* __restrict__ w1f,
    __half* __restrict__ w2f, __half* __restrict__ w3f)
{
    int i = blockIdx.x * 256 + threadIdx.x;
    const float* src;
    __half* dst;
    int off;
    if      (i < C_X)  { src = x;  dst = xf;  off = i; }
    else if (i < C_W1) { src = W1; dst = w1f; off = i - C_X; }
    else if (i < C_W2) { src = W2; dst = w2f; off = i - C_W1; }
    else if (i < C_W3) { src = W3; dst = w3f; off = i - C_W2; }
    else return;

    float4 a = __ldcs(reinterpret_cast<const float4*>(src) + 2 * off);
    float4 b = __ldcs(reinterpret_cast<const float4*>(src) + 2 * off + 1);
    __half2 h0 = __floats2half2_rn(a.x, a.y);
    __half2 h1 = __floats2half2_rn(a.z, a.w);
    __half2 h2 = __floats2half2_rn(b.x, b.y);
    __half2 h3 = __floats2half2_rn(b.z, b.w);
    uint4 o = make_uint4(*reinterpret_cast<uint32_t*>(&h0),
                         *reinterpret_cast<uint32_t*>(&h1),
                         *reinterpret_cast<uint32_t*>(&h2),
                         *reinterpret_cast<uint32_t*>(&h3));
    __stcs(reinterpret_cast<uint4*>(dst) + off, o);
}

// ---------------------------------------------------------------------------
// Helpers (portable to base sm_103: mma.sync + cp.async + ldmatrix)
// ---------------------------------------------------------------------------
__device__ __forceinline__ uint32_t smem_u32(const void* p) {
    uint32_t a;
    asm("{ .reg .u64 t; cvta.to.shared.u64 t, %1; cvt.u32.u64 %0, t; }"
        : "=r"(a) : "l"(p));
    return a;
}
__device__ __forceinline__ void cp16(uint32_t dst, const void* src, bool pred) {
    int sz = pred ? 16 : 0;
    asm volatile("cp.async.cg.shared.global [%0], [%1], 16, %2;"
                 :: "r"(dst), "l"(src), "r"(sz) : "memory");
}
__device__ __forceinline__ void mma16816(float* c, const uint32_t* a,
                                         const uint32_t* b) {
    asm volatile(
        "mma.sync.aligned.m16n8k16.row.col.f32.f16.f16.f32 "
        "{%0,%1,%2,%3}, {%4,%5,%6,%7}, {%8,%9}, {%0,%1,%2,%3};"
        : "+f"(c[0]), "+f"(c[1]), "+f"(c[2]), "+f"(c[3])
        : "r"(a[0]), "r"(a[1]), "r"(a[2]), "r"(a[3]), "r"(b[0]), "r"(b[1]));
}
__device__ __forceinline__ void ldsm4(uint32_t* r, uint32_t addr) {
    asm volatile("ldmatrix.sync.aligned.m8n8.x4.shared.b16 {%0,%1,%2,%3}, [%4];"
                 : "=r"(r[0]), "=r"(r[1]), "=r"(r[2]), "=r"(r[3]) : "r"(addr));
}

constexpr int BM = 128, BN = 128, BK = 32;
constexpr int ROWB  = BK * 2;            // 64 bytes per smem row
constexpr int ARR   = BM * ROWB;         // 8KB per array (Af / Bf)
constexpr int STAGE = 2 * ARR;           // 16KB
constexpr int NST   = 4;
constexpr int SMEM_TOTAL = NST * STAGE;  // 64KB -> 2 CTAs/SM
constexpr int THREADS = 128;             // 4 warps, 2x2, 64x64 warp tiles

// swizzle: 16B slot XOR'd by (row>>1)&3 — conflict-free for ldmatrix 8-row
// groups. XOR applied to the FINAL column (incl. K-half offset): no carry.
__device__ __forceinline__ uint32_t swz_off(uint32_t row, uint32_t col) {
    return row * ROWB + (col ^ (((row >> 1) & 3u) << 4));
}

// ---------------------------------------------------------------------------
// fp16 GEMM on mma.sync + ldmatrix: Out[m,n] = epi( Af[m,:].Wf[n,:] + bias )
// Epilogue: +bias, relu, *scale, += addH, fp32 store OR fp16 store.
// GATE: rows gathered/scattered via g_perm segment blockIdx.z, W offset by gate.
// ---------------------------------------------------------------------------
template<bool GATE>
__global__ __launch_bounds__(THREADS, 2)
void mma_gemm(const __half* __restrict__ Af,
              const __half* __restrict__ Wf_,
              const float* __restrict__ bias_,
              float* __restrict__ outF,
              __half* __restrict__ outH,
              const __half* __restrict__ addH,
              int Nout, int K, int do_relu, float scale)
{
    extern __shared__ char smem[];
    const uint32_t sb = smem_u32(smem);
    const int tid = threadIdx.x, wid = tid >> 5, lid = tid & 31;

    int rowStart, rowValid;
    const __half* Wf = Wf_;
    const float* bp = bias_;
    if (GATE) {
        int g = blockIdx.z;
        int s0 = g_off[g], s1 = g_off[g + 1];
        rowStart = s0 + blockIdx.y * BM;
        if (rowStart >= s1) return;
        rowValid = min(BM, s1 - rowStart);
        Wf += (size_t)g * Nout * K;
        if (bp) bp += (size_t)g * Nout;
    } else {
        rowStart = blockIdx.y * BM;
        rowValid = BM;
    }
    const int cb = blockIdx.x * BN;

    // ---- cp.async mapping: 128 threads x 4 iters cover 512 chunks per array
    const __half* pAf[4];
    const __half* pBf[4];
    bool vA[4];
    uint32_t dOf[4];
#pragma unroll
    for (int i = 0; i < 4; i++) {
        int cid = tid + i * THREADS;
        int r = cid >> 2, c16 = cid & 3;
        dOf[i] = swz_off(r, c16 * 16);
        int ar;
        if (GATE) { ar = (r < rowValid) ? g_perm[rowStart + r] : -1; }
        else      { ar = rowStart + r; }
        vA[i] = ar >= 0;
        pAf[i] = Af + (vA[i] ? (size_t)ar * K : 0) + c16 * 8;
        pBf[i] = Wf + (size_t)(cb + r) * K + c16 * 8;
    }

    const int T = K / BK;
    auto load_tile = [&](int kt) {
        uint32_t st = sb + (kt % NST) * STAGE;
        int ke = kt * BK;
#pragma unroll
        for (int i = 0; i < 4; i++) {
            cp16(st + 0 * ARR + dOf[i], pAf[i] + ke, vA[i]);
            cp16(st + 1 * ARR + dOf[i], pBf[i] + ke, true);
        }
        asm volatile("cp.async.commit_group;" ::: "memory");
    };

    float acc[4][8][4];
#pragma unroll
    for (int a = 0; a < 4; a++)
#pragma unroll
        for (int b = 0; b < 8; b++)
#pragma unroll
            for (int c = 0; c < 4; c++) acc[a][b][c] = 0.f;

    // warp tiling: 2x2 warps, 64x64 per warp
    const int wm = (wid >> 1) * 64;
    const int wn = (wid & 1) * 64;
    const int lg = lid >> 3, l7 = lid & 7;

    // ldmatrix lane components: row offset + mask separate from column so the
    // K-half offset is added BEFORE the swizzle XOR (no carry into row bits).
    uint32_t rowA[4], mskA[4], rowB[4], mskB[4];
    const uint32_t colA = (uint32_t)(lg >> 1) << 4;
    const uint32_t colB = (uint32_t)(lg & 1) << 4;
#pragma unroll
    for (int mt = 0; mt < 4; mt++) {
        uint32_t row = wm + mt * 16 + ((lg & 1) << 3) + l7;
        rowA[mt] = row * ROWB;
        mskA[mt] = ((row >> 1) & 3u) << 4;
    }
#pragma unroll
    for (int np = 0; np < 4; np++) {
        uint32_t row = wn + np * 16 + ((lg >> 1) << 3) + l7;
        rowB[np] = row * ROWB;
        mskB[np] = ((row >> 1) & 3u) << 4;
    }

    load_tile(0);
    load_tile(1);
    load_tile(2);

    for (int kt = 0; kt < T; kt++) {
        if (kt < T - 2)       asm volatile("cp.async.wait_group 2;" ::: "memory");
        else if (kt == T - 2) asm volatile("cp.async.wait_group 1;" ::: "memory");
        else                  asm volatile("cp.async.wait_group 0;" ::: "memory");
        __syncthreads();
        if (kt + 3 < T) load_tile(kt + 3);

        const uint32_t S = sb + (kt % NST) * STAGE;
#pragma unroll
        for (int kh = 0; kh < 2; kh++) {
            const uint32_t kof = kh * 32;
            uint32_t af[4][4], bf[4][4];
#pragma unroll
            for (int mt = 0; mt < 4; mt++) {
                uint32_t off = rowA[mt] + ((colA + kof) ^ mskA[mt]);
                ldsm4(af[mt], S + 0 * ARR + off);
            }
#pragma unroll
            for (int np = 0; np < 4; np++) {
                uint32_t off = rowB[np] + ((colB + kof) ^ mskB[np]);
                ldsm4(bf[np], S + 1 * ARR + off);
            }
#pragma unroll
            for (int mt = 0; mt < 4; mt++) {
#pragma unroll
                for (int np = 0; np < 4; np++) {
                    // np covers nt = 2np (regs 0,1) and nt = 2np+1 (regs 2,3)
                    mma16816(acc[mt][2 * np],     af[mt], &bf[np][0]);
                    mma16816(acc[mt][2 * np + 1], af[mt], &bf[np][2]);
                }
            }
        }
    }

    // ------------------------------- epilogue ------------------------------
    const int gr = lid >> 2;
#pragma unroll
    for (int mt = 0; mt < 4; mt++) {
#pragma unroll
        for (int half = 0; half < 2; half++) {
            const int rloc = wm + mt * 16 + gr + half * 8;
            int grow;
            bool valid = true;
            if (GATE) {
                valid = (rloc < rowValid);
                grow = valid ? g_perm[rowStart + rloc] : 0;
            } else {
                grow = rowStart + rloc;
            }
            if (!valid) continue;
#pragma unroll
            for (int nt = 0; nt < 8; nt++) {
                const int col = cb + wn + nt * 8 + (lid & 3) * 2;
                float v0 = acc[mt][nt][half * 2 + 0];
                float v1 = acc[mt][nt][half * 2 + 1];
                if (bp) {
                    float2 bb = *(const float2*)(bp + col);
                    v0 += bb.x; v1 += bb.y;
                }
                if (do_relu) { v0 = fmaxf(v0, 0.f); v1 = fmaxf(v1, 0.f); }
                v0 *= scale; v1 *= scale;
                const size_t rb = (size_t)grow * Nout + col;
                if (addH) {
                    uint32_t uh = *(const uint32_t*)(addH + rb);
                    float2 fh = __half22float2(*reinterpret_cast<__half2*>(&uh));
                    v0 += fh.x; v1 += fh.y;
                }
                if (outF) {
                    *(float2*)(outF + rb) = make_float2(v0, v1);
                } else {
                    uint32_t ph = (uint32_t)__half_as_ushort(__float2half_rn(v0)) |
                                  ((uint32_t)__half_as_ushort(__float2half_rn(v1)) << 16);
                    *(uint32_t*)(outH + rb) = ph;
                }
            }
        }
    }
}

// ---------------------------------------------------------------------------
extern "C" void kernel_launch(void* const* d_in, const int* in_sizes, int n_in,
                              void* d_out, int out_size) {
    const float* x   = (const float*)d_in[0];
    const int*   gid = (const int*)  d_in[1];
    const float* W1  = (const float*)d_in[2];
    const float* b1  = (const float*)d_in[3];
    const float* W2  = (const float*)d_in[4];
    const float* b2  = (const float*)d_in[5];
    const float* W3  = (const float*)d_in[6];
    float* out = (float*)d_out;

    __half *xf, *w1f, *w2f, *w3f, *sf, *h2f;
    cudaGetSymbolAddress((void**)&xf,  g_xf);
    cudaGetSymbolAddress((void**)&w1f, g_W1f);
    cudaGetSymbolAddress((void**)&w2f, g_W2f);
    cudaGetSymbolAddress((void**)&w3f, g_W3f);
    cudaGetSymbolAddress((void**)&sf,  g_sf);
    cudaGetSymbolAddress((void**)&h2f, g_h2f);

    cudaFuncSetAttribute((const void*)mma_gemm<true>,
                         cudaFuncAttributeMaxDynamicSharedMemorySize, SMEM_TOTAL);
    cudaFuncSetAttribute((const void*)mma_gemm<false>,
                         cudaFuncAttributeMaxDynamicSharedMemorySize, SMEM_TOTAL);

    sort_gates<<<1, 256>>>(gid);

    // one fused streaming conversion kernel: 1 chunk (8 floats) per thread
    conv_all<<<(C_W3 + 255) / 256, 256>>>(x, W1, W2, W3, xf, w1f, w2f, w3f);

    // L1 gate blocks: s = 0.9*relu(x @ W1_g^T + b1_g), rows scattered via perm
    mma_gemm<true><<<dim3(TWOD / BN, NROWS / BM, NGATE), THREADS, SMEM_TOTAL>>>(
        xf, w1f, b1,
        nullptr, sf, nullptr,
        TWOD, INDIM, /*relu=*/1, /*scale=*/0.9f);

    // L1 shared block: s += relu(x @ W1_sh^T + b1_sh)
    mma_gemm<false><<<dim3(TWOD / BN, NROWS / BM), THREADS, SMEM_TOTAL>>>(
        xf,
        w1f + (size_t)NGATE * TWOD * INDIM,
        b1 + (size_t)NGATE * TWOD,
        nullptr, sf, sf,
        TWOD, INDIM, /*relu=*/1, /*scale=*/1.0f);

    // L2: h2 = relu(s @ W2^T + b2)
    mma_gemm<false><<<dim3(DDIM / BN, NROWS / BM), THREADS, SMEM_TOTAL>>>(
        sf, w2f, b2,
        nullptr, h2f, nullptr,
        DDIM, TWOD, /*relu=*/1, /*scale=*/1.0f);

    // L3: out = h2 @ W3^T  (fp32 store)
    mma_gemm<false><<<dim3(OUTDIM / BN, NROWS / BM), THREADS, SMEM_TOTAL>>>(
        h2f, w3f, nullptr,
        out, nullptr, nullptr,
        OUTDIM, DDIM, /*relu=*/0, /*scale=*/1.0f);
}